// round 5
// baseline (speedup 1.0000x reference)
#include <cuda_runtime.h>
#include <cuda_bf16.h>
#include <math.h>

#define BB 256
#define HH 512
#define EE 512
#define VV 10000
#define TT 48
#define TTOT 9436
#define NBLK 128

// ---------------- scratch (device globals; no allocation allowed) -------------
__device__ float g_Xc[BB * 2048];          // conv output flattened [B,2048]
__device__ float g_F0[BB * HH];            // pre-BN fc output
__device__ float g_F[BB * HH];             // BN'd features
__device__ float g_Emb[TTOT * EE];         // packed caption embeddings
__device__ float g_xA[TT * BB * HH];
__device__ float g_xC[TT * BB * HH];
__device__ float g_hx[BB * HH];
__device__ float g_GhL[BB * 2048];         // [Gh(1536) | attn logits h-part(512)]
__device__ float g_Gi[BB * 3 * HH];
__device__ float g_applied[BB * HH];
__device__ float g_inp[BB * HH];
__device__ float g_Cat[BB * 2 * HH];
__device__ float g_Y[BB * 2 * HH];

// pre-split packed bf16 weight buffers (H = hi, L = lo), k packed 2/uint
__device__ unsigned g_fcwH[512 * 1024],  g_fcwL[512 * 1024];    // fc_w K=2048
__device__ unsigned g_fc2H[512 * 5000],  g_fc2L[512 * 5000];    // fc2_w K=10000
__device__ unsigned g_atxH[512 * 256],   g_atxL[512 * 256];     // attn_w[:, :512]
__device__ unsigned g_cbxH[512 * 256],   g_cbxL[512 * 256];     // comb_w[:, :512]
__device__ unsigned g_cbhH[512 * 256],   g_cbhL[512 * 256];     // comb_w[:, 512:]
__device__ unsigned g_wihH[1536 * 256],  g_wihL[1536 * 256];    // gru_wih
__device__ unsigned g_linH[1024 * 512],  g_linL[1024 * 512];    // lin_w K=1024
__device__ unsigned g_wpkH[2048 * 256],  g_wpkL[2048 * 256];    // [whh ; attn_wh]
__device__ unsigned g_XpH[TT * BB * 256], g_XpL[TT * BB * 256]; // split Xpad

// global software barrier state
__device__ int g_bar_count;
__device__ volatile int g_bar_phase;

// ---------------- bf16 helpers -------------------------------------------------
__device__ __forceinline__ void mma_bf16(float c[4],
    unsigned a0, unsigned a1, unsigned a2, unsigned a3,
    unsigned b0, unsigned b1)
{
    asm volatile(
        "mma.sync.aligned.m16n8k16.row.col.f32.bf16.bf16.f32 "
        "{%0,%1,%2,%3}, {%4,%5,%6,%7}, {%8,%9}, {%0,%1,%2,%3};"
        : "+f"(c[0]), "+f"(c[1]), "+f"(c[2]), "+f"(c[3])
        : "r"(a0), "r"(a1), "r"(a2), "r"(a3), "r"(b0), "r"(b1));
}

__device__ __forceinline__ void split2(float a, float b, unsigned& h, unsigned& l)
{
    __nv_bfloat16 ha = __float2bfloat16_rn(a), hb = __float2bfloat16_rn(b);
    __nv_bfloat16 la = __float2bfloat16_rn(a - __bfloat162float(ha));
    __nv_bfloat16 lb = __float2bfloat16_rn(b - __bfloat162float(hb));
    __nv_bfloat162 th = __halves2bfloat162(ha, hb);
    __nv_bfloat162 tl = __halves2bfloat162(la, lb);
    h = *reinterpret_cast<unsigned*>(&th);
    l = *reinterpret_cast<unsigned*>(&tl);
}

__device__ __forceinline__ void split4u(const float4 v,
    unsigned& h0, unsigned& h1, unsigned& l0, unsigned& l1)
{
    split2(v.x, v.y, h0, l0);
    split2(v.z, v.w, h1, l1);
}

// =================== GEMM compute core ===============
#define GEMM_COMPUTE()                                                          \
    {                                                                           \
        unsigned ah[2][4], al_[2][4], bh[4][2], bl[4][2];                       \
        _Pragma("unroll")                                                       \
        for (int mt = 0; mt < 2; mt++) {                                        \
            int r = wm + mt * 16 + krow;                                        \
            int o0 = r * 12 + kcol;                                             \
            int o1 = (r + 8) * 12 + kcol;                                       \
            ah[mt][0] = Ah[o0];     ah[mt][1] = Ah[o1];                         \
            ah[mt][2] = Ah[o0 + 4]; ah[mt][3] = Ah[o1 + 4];                     \
            al_[mt][0] = Al[o0];     al_[mt][1] = Al[o1];                       \
            al_[mt][2] = Al[o0 + 4]; al_[mt][3] = Al[o1 + 4];                   \
        }                                                                       \
        _Pragma("unroll")                                                       \
        for (int nt = 0; nt < 4; nt++) {                                        \
            int cn = wn + nt * 8 + krow;                                        \
            int o = cn * 12 + kcol;                                             \
            bh[nt][0] = Wh[o]; bh[nt][1] = Wh[o + 4];                           \
            bl[nt][0] = Wl[o]; bl[nt][1] = Wl[o + 4];                           \
        }                                                                       \
        _Pragma("unroll")                                                       \
        for (int mt = 0; mt < 2; mt++)                                          \
            _Pragma("unroll")                                                   \
            for (int nt = 0; nt < 4; nt++) {                                    \
                mma_bf16(acc[mt][nt], ah[mt][0], ah[mt][1], ah[mt][2],          \
                         ah[mt][3], bh[nt][0], bh[nt][1]);                      \
                mma_bf16(acc[mt][nt], ah[mt][0], ah[mt][1], ah[mt][2],          \
                         ah[mt][3], bl[nt][0], bl[nt][1]);                      \
                mma_bf16(acc[mt][nt], al_[mt][0], al_[mt][1], al_[mt][2],       \
                         al_[mt][3], bh[nt][0], bh[nt][1]);                     \
            }                                                                   \
    }

// ---------------- hgemm: A fp32 (split in-kernel), W pre-split -----------------
__global__ __launch_bounds__(128) void hgemm_kernel(
    const float* __restrict__ A, int lda,
    const unsigned* __restrict__ WhP, const unsigned* __restrict__ WlP, int ldwU,
    const float* __restrict__ bias,
    const float* __restrict__ add,
    float* __restrict__ C, int ldc,
    int M, int N, int K, int act)
{
    __shared__ unsigned Ah[64 * 12], Al[64 * 12];
    __shared__ unsigned Wh[64 * 12], Wl[64 * 12];

    const int tid  = threadIdx.x;
    const int lane = tid & 31;
    const int warp = tid >> 5;
    const int wm = (warp & 1) * 32;
    const int wn = (warp >> 1) * 32;
    const int m0 = blockIdx.y * 64;
    const int n0 = blockIdx.x * 64;
    const int lr = tid >> 2;
    const int lc = (tid & 3) * 4;
    const int lcu = lc >> 1;
    const int krow = lane >> 2;
    const int kcol = lane & 3;

    float acc[2][4][4];
#pragma unroll
    for (int mt = 0; mt < 2; mt++)
#pragma unroll
        for (int nt = 0; nt < 4; nt++)
#pragma unroll
            for (int i = 0; i < 4; i++) acc[mt][nt][i] = 0.f;

    const int ar0 = m0 + lr, ar1 = m0 + lr + 32;
    const int wr0 = n0 + lr, wr1 = n0 + lr + 32;
    const float4 z4 = make_float4(0.f, 0.f, 0.f, 0.f);

    float4 av0, av1;
    uint2 wv0h, wv0l, wv1h, wv1l;
    av0 = (ar0 < M) ? *(const float4*)(A + (size_t)ar0 * lda + lc) : z4;
    av1 = (ar1 < M) ? *(const float4*)(A + (size_t)ar1 * lda + lc) : z4;
    wv0h = *(const uint2*)(WhP + (size_t)wr0 * ldwU + lcu);
    wv0l = *(const uint2*)(WlP + (size_t)wr0 * ldwU + lcu);
    wv1h = *(const uint2*)(WhP + (size_t)wr1 * ldwU + lcu);
    wv1l = *(const uint2*)(WlP + (size_t)wr1 * ldwU + lcu);

    for (int kk = 0; kk < K; kk += 16) {
        {
            unsigned h0, h1, l0, l1;
            split4u(av0, h0, h1, l0, l1);
            *(uint2*)&Ah[lr * 12 + lcu] = make_uint2(h0, h1);
            *(uint2*)&Al[lr * 12 + lcu] = make_uint2(l0, l1);
            split4u(av1, h0, h1, l0, l1);
            *(uint2*)&Ah[(lr + 32) * 12 + lcu] = make_uint2(h0, h1);
            *(uint2*)&Al[(lr + 32) * 12 + lcu] = make_uint2(l0, l1);
            *(uint2*)&Wh[lr * 12 + lcu] = wv0h;
            *(uint2*)&Wl[lr * 12 + lcu] = wv0l;
            *(uint2*)&Wh[(lr + 32) * 12 + lcu] = wv1h;
            *(uint2*)&Wl[(lr + 32) * 12 + lcu] = wv1l;
        }
        __syncthreads();

        if (kk + 16 < K) {
            int k2 = kk + 16 + lc;
            int k2u = k2 >> 1;
            av0 = (ar0 < M) ? *(const float4*)(A + (size_t)ar0 * lda + k2) : z4;
            av1 = (ar1 < M) ? *(const float4*)(A + (size_t)ar1 * lda + k2) : z4;
            wv0h = *(const uint2*)(WhP + (size_t)wr0 * ldwU + k2u);
            wv0l = *(const uint2*)(WlP + (size_t)wr0 * ldwU + k2u);
            wv1h = *(const uint2*)(WhP + (size_t)wr1 * ldwU + k2u);
            wv1l = *(const uint2*)(WlP + (size_t)wr1 * ldwU + k2u);
        }

        GEMM_COMPUTE();
        __syncthreads();
    }

#pragma unroll
    for (int mt = 0; mt < 2; mt++) {
#pragma unroll
        for (int nt = 0; nt < 4; nt++) {
            int r0 = m0 + wm + mt * 16 + (lane >> 2);
            int c0 = n0 + wn + nt * 8 + (lane & 3) * 2;
#pragma unroll
            for (int i = 0; i < 4; i++) {
                int row = r0 + (i >> 1) * 8;
                int col = c0 + (i & 1);
                if (row >= M) continue;
                float v = acc[mt][nt][i];
                if (bias) v += bias[col];
                if (add)  v += add[(size_t)row * ldc + col];
                if (act)  v = fmaxf(v, 0.f);
                C[(size_t)row * ldc + col] = v;
            }
        }
    }
}

// ---------------- pgemm: both A and W pre-split --------------------------------
__global__ __launch_bounds__(128) void pgemm_kernel(
    const unsigned* __restrict__ AhP, const unsigned* __restrict__ AlP, int ldaU,
    const unsigned* __restrict__ WhP, const unsigned* __restrict__ WlP, int ldwU,
    const float* __restrict__ bias,
    const float* __restrict__ add,
    float* __restrict__ C, int ldc,
    int M, int N, int K, int act)
{
    __shared__ unsigned Ah[64 * 12], Al[64 * 12];
    __shared__ unsigned Wh[64 * 12], Wl[64 * 12];

    const int tid  = threadIdx.x;
    const int lane = tid & 31;
    const int warp = tid >> 5;
    const int wm = (warp & 1) * 32;
    const int wn = (warp >> 1) * 32;
    const int m0 = blockIdx.y * 64;
    const int n0 = blockIdx.x * 64;
    const int lr = tid >> 2;
    const int lcu = (tid & 3) * 2;
    const int krow = lane >> 2;
    const int kcol = lane & 3;

    float acc[2][4][4];
#pragma unroll
    for (int mt = 0; mt < 2; mt++)
#pragma unroll
        for (int nt = 0; nt < 4; nt++)
#pragma unroll
            for (int i = 0; i < 4; i++) acc[mt][nt][i] = 0.f;

    const int ar0 = m0 + lr, ar1 = m0 + lr + 32;
    const int wr0 = n0 + lr, wr1 = n0 + lr + 32;
    const uint2 zu = make_uint2(0u, 0u);

    uint2 a0h, a0l, a1h, a1l, w0h, w0l, w1h, w1l;
    a0h = (ar0 < M) ? *(const uint2*)(AhP + (size_t)ar0 * ldaU + lcu) : zu;
    a0l = (ar0 < M) ? *(const uint2*)(AlP + (size_t)ar0 * ldaU + lcu) : zu;
    a1h = (ar1 < M) ? *(const uint2*)(AhP + (size_t)ar1 * ldaU + lcu) : zu;
    a1l = (ar1 < M) ? *(const uint2*)(AlP + (size_t)ar1 * ldaU + lcu) : zu;
    w0h = *(const uint2*)(WhP + (size_t)wr0 * ldwU + lcu);
    w0l = *(const uint2*)(WlP + (size_t)wr0 * ldwU + lcu);
    w1h = *(const uint2*)(WhP + (size_t)wr1 * ldwU + lcu);
    w1l = *(const uint2*)(WlP + (size_t)wr1 * ldwU + lcu);

    for (int kk = 0; kk < K; kk += 16) {
        *(uint2*)&Ah[lr * 12 + lcu] = a0h;
        *(uint2*)&Al[lr * 12 + lcu] = a0l;
        *(uint2*)&Ah[(lr + 32) * 12 + lcu] = a1h;
        *(uint2*)&Al[(lr + 32) * 12 + lcu] = a1l;
        *(uint2*)&Wh[lr * 12 + lcu] = w0h;
        *(uint2*)&Wl[lr * 12 + lcu] = w0l;
        *(uint2*)&Wh[(lr + 32) * 12 + lcu] = w1h;
        *(uint2*)&Wl[(lr + 32) * 12 + lcu] = w1l;
        __syncthreads();

        if (kk + 16 < K) {
            int k2u = (kk + 16) / 2 + lcu;
            a0h = (ar0 < M) ? *(const uint2*)(AhP + (size_t)ar0 * ldaU + k2u) : zu;
            a0l = (ar0 < M) ? *(const uint2*)(AlP + (size_t)ar0 * ldaU + k2u) : zu;
            a1h = (ar1 < M) ? *(const uint2*)(AhP + (size_t)ar1 * ldaU + k2u) : zu;
            a1l = (ar1 < M) ? *(const uint2*)(AlP + (size_t)ar1 * ldaU + k2u) : zu;
            w0h = *(const uint2*)(WhP + (size_t)wr0 * ldwU + k2u);
            w0l = *(const uint2*)(WlP + (size_t)wr0 * ldwU + k2u);
            w1h = *(const uint2*)(WhP + (size_t)wr1 * ldwU + k2u);
            w1l = *(const uint2*)(WlP + (size_t)wr1 * ldwU + k2u);
        }

        GEMM_COMPUTE();
        __syncthreads();
    }

#pragma unroll
    for (int mt = 0; mt < 2; mt++) {
#pragma unroll
        for (int nt = 0; nt < 4; nt++) {
            int r0 = m0 + wm + mt * 16 + (lane >> 2);
            int c0 = n0 + wn + nt * 8 + (lane & 3) * 2;
#pragma unroll
            for (int i = 0; i < 4; i++) {
                int row = r0 + (i >> 1) * 8;
                int col = c0 + (i & 1);
                if (row >= M) continue;
                float v = acc[mt][nt][i];
                if (bias) v += bias[col];
                if (add)  v += add[(size_t)row * ldc + col];
                if (act)  v = fmaxf(v, 0.f);
                C[(size_t)row * ldc + col] = v;
            }
        }
    }
}

// ======================= persistent scan kernel =================================
// one 64x64 tile, A fp32 via __ldcg (cross-phase data), W pre-split (L1-cached)
__device__ __forceinline__ void gemm_tile(
    const float* __restrict__ A, int lda,
    const unsigned* __restrict__ WhP, const unsigned* __restrict__ WlP, int ldwU,
    const float* __restrict__ bias, const float* __restrict__ add,
    float* __restrict__ C, int ldc, int K, int m0, int n0, int act,
    unsigned* Ah, unsigned* Al, unsigned* Wh, unsigned* Wl)
{
    const int tid  = threadIdx.x;
    const int lane = tid & 31;
    const int warp = tid >> 5;
    const int wm = (warp & 1) * 32;
    const int wn = (warp >> 1) * 32;
    const int lr = tid >> 2;
    const int lc = (tid & 3) * 4;
    const int lcu = lc >> 1;
    const int krow = lane >> 2;
    const int kcol = lane & 3;

    float acc[2][4][4];
#pragma unroll
    for (int mt = 0; mt < 2; mt++)
#pragma unroll
        for (int nt = 0; nt < 4; nt++)
#pragma unroll
            for (int i = 0; i < 4; i++) acc[mt][nt][i] = 0.f;

    const int ar0 = m0 + lr, ar1 = m0 + lr + 32;
    const int wr0 = n0 + lr, wr1 = n0 + lr + 32;

    float4 av0 = __ldcg((const float4*)(A + (size_t)ar0 * lda + lc));
    float4 av1 = __ldcg((const float4*)(A + (size_t)ar1 * lda + lc));
    uint2 wv0h = *(const uint2*)(WhP + (size_t)wr0 * ldwU + lcu);
    uint2 wv0l = *(const uint2*)(WlP + (size_t)wr0 * ldwU + lcu);
    uint2 wv1h = *(const uint2*)(WhP + (size_t)wr1 * ldwU + lcu);
    uint2 wv1l = *(const uint2*)(WlP + (size_t)wr1 * ldwU + lcu);

    for (int kk = 0; kk < K; kk += 16) {
        {
            unsigned h0, h1, l0, l1;
            split4u(av0, h0, h1, l0, l1);
            *(uint2*)&Ah[lr * 12 + lcu] = make_uint2(h0, h1);
            *(uint2*)&Al[lr * 12 + lcu] = make_uint2(l0, l1);
            split4u(av1, h0, h1, l0, l1);
            *(uint2*)&Ah[(lr + 32) * 12 + lcu] = make_uint2(h0, h1);
            *(uint2*)&Al[(lr + 32) * 12 + lcu] = make_uint2(l0, l1);
            *(uint2*)&Wh[lr * 12 + lcu] = wv0h;
            *(uint2*)&Wl[lr * 12 + lcu] = wv0l;
            *(uint2*)&Wh[(lr + 32) * 12 + lcu] = wv1h;
            *(uint2*)&Wl[(lr + 32) * 12 + lcu] = wv1l;
        }
        __syncthreads();

        if (kk + 16 < K) {
            int k2 = kk + 16 + lc;
            int k2u = k2 >> 1;
            av0 = __ldcg((const float4*)(A + (size_t)ar0 * lda + k2));
            av1 = __ldcg((const float4*)(A + (size_t)ar1 * lda + k2));
            wv0h = *(const uint2*)(WhP + (size_t)wr0 * ldwU + k2u);
            wv0l = *(const uint2*)(WlP + (size_t)wr0 * ldwU + k2u);
            wv1h = *(const uint2*)(WhP + (size_t)wr1 * ldwU + k2u);
            wv1l = *(const uint2*)(WlP + (size_t)wr1 * ldwU + k2u);
        }

        GEMM_COMPUTE();
        __syncthreads();
    }

#pragma unroll
    for (int mt = 0; mt < 2; mt++) {
#pragma unroll
        for (int nt = 0; nt < 4; nt++) {
            int r0 = m0 + wm + mt * 16 + (lane >> 2);
            int c0 = n0 + wn + nt * 8 + (lane & 3) * 2;
#pragma unroll
            for (int i = 0; i < 4; i++) {
                int row = r0 + (i >> 1) * 8;
                int col = c0 + (i & 1);
                float v = acc[mt][nt][i];
                if (bias) v += bias[col];
                if (add)  v += add[(size_t)row * ldc + col];
                if (act)  v = fmaxf(v, 0.f);
                C[(size_t)row * ldc + col] = v;
            }
        }
    }
}

__device__ __forceinline__ void grid_sync(int& gen)
{
    __syncthreads();
    if (threadIdx.x == 0) {
        __threadfence();
        if (atomicAdd(&g_bar_count, 1) == NBLK - 1) {
            g_bar_count = 0;
            __threadfence();
            g_bar_phase = gen + 1;
        } else {
            while (g_bar_phase - gen < 1) { }
        }
    }
    __syncthreads();
    gen++;
}

__global__ __launch_bounds__(128) void scan_kernel(
    const int* __restrict__ lengths,
    const float* __restrict__ gru_bih,
    const float* __restrict__ gru_bhh,
    float* __restrict__ hiddens)
{
    __shared__ unsigned Ah[64 * 12], Al[64 * 12];
    __shared__ unsigned Wh[64 * 12], Wl[64 * 12];
    __shared__ float s_red[128];

    const int tid = threadIdx.x;
    const int bid = blockIdx.x;
    int gen = g_bar_phase;      // stable before first barrier

    for (int t = 0; t < TT; t++) {
        // ---- P1: GhL = hx @ Wpack^T (128 tiles, 1 per block) ----
        {
            int mg = bid >> 5, nt = bid & 31;
            gemm_tile(g_hx, HH, g_wpkH, g_wpkL, 256, nullptr, nullptr,
                      g_GhL, 2048, HH, mg * 64, nt * 64, 0, Ah, Al, Wh, Wl);
        }
        grid_sync(gen);

        // ---- P2: softmax over GhL L-part + xA, gate F -> applied ----
        for (int rr = 0; rr < 2; rr++) {
            int r = bid * 2 + rr;
            float v[4];
#pragma unroll
            for (int i = 0; i < 4; i++) {
                int h = tid + i * 128;
                v[i] = __ldcg(&g_GhL[(size_t)r * 2048 + 1536 + h])
                     + g_xA[((size_t)t * BB + r) * HH + h];
            }
            float mx = fmaxf(fmaxf(v[0], v[1]), fmaxf(v[2], v[3]));
            s_red[tid] = mx;
            __syncthreads();
            for (int s = 64; s > 0; s >>= 1) {
                if (tid < s) s_red[tid] = fmaxf(s_red[tid], s_red[tid + s]);
                __syncthreads();
            }
            mx = s_red[0];
            __syncthreads();
            float e[4];
            float sum = 0.f;
#pragma unroll
            for (int i = 0; i < 4; i++) { e[i] = expf(v[i] - mx); sum += e[i]; }
            s_red[tid] = sum;
            __syncthreads();
            for (int s = 64; s > 0; s >>= 1) {
                if (tid < s) s_red[tid] += s_red[tid + s];
                __syncthreads();
            }
            float inv = 1.f / s_red[0];
            __syncthreads();
#pragma unroll
            for (int i = 0; i < 4; i++) {
                int h = tid + i * 128;
                g_applied[(size_t)r * HH + h] =
                    g_F[(size_t)r * HH + h] * (e[i] * inv);
            }
        }
        grid_sync(gen);

        // ---- P3: inp = relu(xC[t] + applied @ comb_wh^T) (32 tiles) ----
        if (bid < 32) {
            int mg = bid >> 3, nt = bid & 7;
            gemm_tile(g_applied, HH, g_cbhH, g_cbhL, 256, nullptr,
                      g_xC + (size_t)t * BB * HH,
                      g_inp, HH, HH, mg * 64, nt * 64, 1, Ah, Al, Wh, Wl);
        }
        grid_sync(gen);

        // ---- P4: Gi = inp @ gru_wih^T + gru_bih (96 tiles) ----
        if (bid < 96) {
            int mg = bid / 24, nt = bid % 24;
            gemm_tile(g_inp, HH, g_wihH, g_wihL, 256, gru_bih, nullptr,
                      g_Gi, 1536, HH, mg * 64, nt * 64, 0, Ah, Al, Wh, Wl);
        }
        grid_sync(gen);

        // ---- P5: GRU gate + hidden update + capture ----
        for (int j = 0; j < 8; j++) {
            int idx = bid * 1024 + j * 128 + tid;
            int b = idx >> 9;
            int h = idx & 511;
            size_t oG = (size_t)b * 2048;
            size_t oI = (size_t)b * 1536;
            float hr = __ldcg(&g_GhL[oG + h])        + gru_bhh[h];
            float hz = __ldcg(&g_GhL[oG + 512 + h])  + gru_bhh[512 + h];
            float hn = __ldcg(&g_GhL[oG + 1024 + h]) + gru_bhh[1024 + h];
            float ir = __ldcg(&g_Gi[oI + h]);
            float iz = __ldcg(&g_Gi[oI + 512 + h]);
            float in_ = __ldcg(&g_Gi[oI + 1024 + h]);
            float rg = 1.f / (1.f + expf(-(ir + hr)));
            float z = 1.f / (1.f + expf(-(iz + hz)));
            float n = tanhf(in_ + rg * hn);
            float hprev = __ldcg(&g_hx[idx]);
            float hnew = (1.f - z) * n + z * hprev;
            g_hx[idx] = hnew;
            if (t == lengths[b] - 1)
                hiddens[idx] = hnew;
        }
        grid_sync(gen);
    }
}

// ---------------- weight split kernels ------------------------------------------
__global__ void split_kernel(const float* __restrict__ src, int srcLd, int colsU,
                             long total, unsigned* __restrict__ H, unsigned* __restrict__ L)
{
    long i = (long)blockIdx.x * 256 + threadIdx.x;
    if (i >= total) return;
    long r = i / colsU;
    int c = (int)(i - r * colsU);
    float a = src[r * srcLd + 2 * c];
    float b = src[r * srcLd + 2 * c + 1];
    split2(a, b, H[i], L[i]);
}

__global__ void wpack_split_kernel(const float* __restrict__ whh,
                                   const float* __restrict__ attn_w)
{
    int i = blockIdx.x * 256 + threadIdx.x;      // 2048*256
    int r = i >> 8, c = i & 255;
    float a, b;
    if (r < 1536) { a = whh[r * 512 + 2 * c]; b = whh[r * 512 + 2 * c + 1]; }
    else { a = attn_w[(r - 1536) * 1024 + 512 + 2 * c];
           b = attn_w[(r - 1536) * 1024 + 512 + 2 * c + 1]; }
    split2(a, b, g_wpkH[i], g_wpkL[i]);
}

// ---------------- direct conv: features[B,2048,8,8] * conv_w[32,2048,3,3], pad1
__global__ __launch_bounds__(256) void conv_kernel(
    const float* __restrict__ features,
    const float* __restrict__ conv_w,
    const float* __restrict__ conv_b)
{
    __shared__ float sF[4][4][100];
    __shared__ float sW[4][4][32][9];
    __shared__ float sRed[2][64][32];

    const int b = blockIdx.x;
    const int tid = threadIdx.x;
    const int qid = tid >> 6;
    const int t2  = tid & 63;
    const int coutg = t2 >> 4;
    const int sg    = t2 & 15;

    for (int e = tid; e < 4 * 4 * 100; e += 256)
        (&sF[0][0][0])[e] = 0.f;

    int fb[4];
#pragma unroll
    for (int sp = 0; sp < 4; sp++) {
        int s = sg * 4 + sp;
        fb[sp] = (s >> 3) * 10 + (s & 7);
    }

    float acc[8][4];
#pragma unroll
    for (int co = 0; co < 8; co++)
#pragma unroll
        for (int sp = 0; sp < 4; sp++) acc[co][sp] = 0.f;

    for (int cbase = 0; cbase < 512; cbase += 4) {
        __syncthreads();
        for (int e = tid; e < 1024; e += 256) {
            int q = e >> 8, c = (e >> 6) & 3, s = e & 63;
            int y = s >> 3, x = s & 7;
            int cin = q * 512 + cbase + c;
            sF[q][c][(y + 1) * 10 + (x + 1)] =
                features[((size_t)b * 2048 + cin) * 64 + s];
        }
        for (int e = tid; e < 4608; e += 256) {
            int q = e / 1152, r = e % 1152;
            int c = r / 288, r2 = r % 288;
            int cout = r2 / 9, k = r2 % 9;
            int cin = q * 512 + cbase + c;
            sW[q][c][cout][k] = conv_w[((size_t)cout * 2048 + cin) * 9 + k];
        }
        __syncthreads();

#pragma unroll
        for (int c = 0; c < 4; c++) {
            const float* fp = &sF[qid][c][0];
            const float* wp = &sW[qid][c][0][0];
#pragma unroll
            for (int ky = 0; ky < 3; ky++) {
#pragma unroll
                for (int kx = 0; kx < 3; kx++) {
                    float wv[8];
#pragma unroll
                    for (int co = 0; co < 8; co++)
                        wv[co] = wp[(coutg * 8 + co) * 9 + ky * 3 + kx];
#pragma unroll
                    for (int sp = 0; sp < 4; sp++) {
                        float fv = fp[fb[sp] + ky * 10 + kx];
#pragma unroll
                        for (int co = 0; co < 8; co++)
                            acc[co][sp] += fv * wv[co];
                    }
                }
            }
        }
    }

    __syncthreads();
    if (qid >= 2) {
#pragma unroll
        for (int co = 0; co < 8; co++)
#pragma unroll
            for (int sp = 0; sp < 4; sp++)
                sRed[qid - 2][t2][co * 4 + sp] = acc[co][sp];
    }
    __syncthreads();
    if (qid < 2) {
#pragma unroll
        for (int co = 0; co < 8; co++)
#pragma unroll
            for (int sp = 0; sp < 4; sp++)
                acc[co][sp] += sRed[qid][t2][co * 4 + sp];
    }
    __syncthreads();
    if (qid == 1) {
#pragma unroll
        for (int co = 0; co < 8; co++)
#pragma unroll
            for (int sp = 0; sp < 4; sp++)
                sRed[0][t2][co * 4 + sp] = acc[co][sp];
    }
    __syncthreads();
    if (qid == 0) {
#pragma unroll
        for (int co = 0; co < 8; co++) {
            int cout = coutg * 8 + co;
            float bval = conv_b[cout];
#pragma unroll
            for (int sp = 0; sp < 4; sp++) {
                int s = sg * 4 + sp;
                g_Xc[(size_t)b * 2048 + cout * 64 + s] =
                    acc[co][sp] + sRed[0][t2][co * 4 + sp] + bval;
            }
        }
    }
}

// ---------------- BatchNorm1d with batch stats ---------------------------------
__global__ void bn_kernel(const float* __restrict__ bn_g,
                          const float* __restrict__ bn_b)
{
    __shared__ float red[256];
    const int h = blockIdx.x;
    const int b = threadIdx.x;
    float v = g_F0[(size_t)b * HH + h];
    red[b] = v;
    __syncthreads();
    for (int s = 128; s > 0; s >>= 1) {
        if (b < s) red[b] += red[b + s];
        __syncthreads();
    }
    float mu = red[0] / 256.f;
    __syncthreads();
    float d = v - mu;
    red[b] = d * d;
    __syncthreads();
    for (int s = 128; s > 0; s >>= 1) {
        if (b < s) red[b] += red[b + s];
        __syncthreads();
    }
    float var = red[0] / 256.f;
    float scale = rsqrtf(var + 1e-5f);
    g_F[(size_t)b * HH + h] = d * scale * bn_g[h] + bn_b[h];
}

// ---------------- gather packed embeddings into split bf16 Xpad ----------------
__global__ void gather_split_kernel(const int* __restrict__ pack_idx)
{
    int tb = blockIdx.x;
    int t = tb >> 8, b = tb & 255;
    int cu = threadIdx.x;
    int idx = pack_idx[b * TT + t];
    float a = 0.f, vb = 0.f;
    if (idx >= 0) {
        a  = g_Emb[(size_t)idx * EE + 2 * cu];
        vb = g_Emb[(size_t)idx * EE + 2 * cu + 1];
    }
    unsigned h, l;
    split2(a, vb, h, l);
    size_t o = (size_t)tb * 256 + cu;
    g_XpH[o] = h; g_XpL[o] = l;
}

__global__ void init_hx_kernel(const float* __restrict__ states)
{
    int i = blockIdx.x * blockDim.x + threadIdx.x;
    g_hx[i] = states[i];
}

// ---------------- build concat [hiddens, F] ------------------------------------
__global__ void cat_kernel(const float* __restrict__ hiddens)
{
    const int b = blockIdx.x;
    const int i = threadIdx.x;
    float v = (i < 512) ? hiddens[(size_t)b * HH + i]
                        : g_F[(size_t)b * HH + (i - 512)];
    g_Cat[(size_t)b * 1024 + i] = v;
}

// ---------------- final linear(1024->1) + sigmoid ------------------------------
__global__ void head_kernel(const float* __restrict__ lin3_w,
                            const float* __restrict__ lin3_b,
                            float* __restrict__ out)
{
    __shared__ float red[256];
    const int b = blockIdx.x;
    const int tid = threadIdx.x;
    float acc = 0.f;
#pragma unroll
    for (int k = 0; k < 4; k++) {
        int idx = tid + k * 256;
        acc += g_Y[(size_t)b * 1024 + idx] * lin3_w[idx];
    }
    red[tid] = acc;
    __syncthreads();
    for (int s = 128; s > 0; s >>= 1) {
        if (tid < s) red[tid] += red[tid + s];
        __syncthreads();
    }
    if (tid == 0) {
        float x = red[0] + lin3_b[0];
        out[b] = 1.f / (1.f + expf(-x));
    }
}

// ---------------- host orchestration ------------------------------------------
static void hgemm(const float* A, int lda, const unsigned* WH, const unsigned* WL,
                  int ldwU, const float* bias, const float* add,
                  float* C, int ldc, int M, int N, int K, int act)
{
    dim3 grid(N / 64, (M + 63) / 64);
    hgemm_kernel<<<grid, 128>>>(A, lda, WH, WL, ldwU, bias, add, C, ldc, M, N, K, act);
}

static void pgemm(const unsigned* AH, const unsigned* AL, int ldaU,
                  const unsigned* WH, const unsigned* WL, int ldwU,
                  const float* bias, const float* add,
                  float* C, int ldc, int M, int N, int K, int act)
{
    dim3 grid(N / 64, (M + 63) / 64);
    pgemm_kernel<<<grid, 128>>>(AH, AL, ldaU, WH, WL, ldwU, bias, add, C, ldc, M, N, K, act);
}

static void split(const float* src, int srcLd, int colsU, long rows,
                  unsigned* H, unsigned* L)
{
    long total = rows * colsU;
    split_kernel<<<(unsigned)((total + 255) / 256), 256>>>(src, srcLd, colsU, total, H, L);
}

extern "C" void kernel_launch(void* const* d_in, const int* in_sizes, int n_in,
                              void* d_out, int out_size)
{
    const float* features = (const float*)d_in[0];
    const float* captions = (const float*)d_in[1];
    const float* states   = (const float*)d_in[2];
    const int*   pack_idx = (const int*)d_in[3];
    const int*   lengths  = (const int*)d_in[4];
    const float* conv_w   = (const float*)d_in[5];
    const float* conv_b   = (const float*)d_in[6];
    const float* fc_w     = (const float*)d_in[7];
    const float* fc_b     = (const float*)d_in[8];
    const float* bn_g     = (const float*)d_in[9];
    const float* bn_b     = (const float*)d_in[10];
    const float* fc2_w    = (const float*)d_in[11];
    const float* fc2_b    = (const float*)d_in[12];
    const float* attn_w   = (const float*)d_in[13];
    const float* attn_b   = (const float*)d_in[14];
    const float* comb_w   = (const float*)d_in[15];
    const float* comb_b   = (const float*)d_in[16];
    const float* gru_wih  = (const float*)d_in[17];
    const float* gru_whh  = (const float*)d_in[18];
    const float* gru_bih  = (const float*)d_in[19];
    const float* gru_bhh  = (const float*)d_in[20];
    const float* lin_w    = (const float*)d_in[21];
    const float* lin_b    = (const float*)d_in[22];
    const float* lin3_w   = (const float*)d_in[23];
    const float* lin3_b   = (const float*)d_in[24];

    float* out = (float*)d_out;            // [0:256) sigmoid, [256: ) hiddens
    float* hiddens = out + 256;

    float *pXc, *pF0, *pEmb, *pxA, *pxC, *pCat, *pY;
    unsigned *fcwH, *fcwL, *fc2H, *fc2L, *atxH, *atxL, *cbxH, *cbxL;
    unsigned *linH, *linL, *XpH, *XpL;
    cudaGetSymbolAddress((void**)&pXc, g_Xc);
    cudaGetSymbolAddress((void**)&pF0, g_F0);
    cudaGetSymbolAddress((void**)&pEmb, g_Emb);
    cudaGetSymbolAddress((void**)&pxA, g_xA);
    cudaGetSymbolAddress((void**)&pxC, g_xC);
    cudaGetSymbolAddress((void**)&pCat, g_Cat);
    cudaGetSymbolAddress((void**)&pY, g_Y);
    cudaGetSymbolAddress((void**)&fcwH, g_fcwH); cudaGetSymbolAddress((void**)&fcwL, g_fcwL);
    cudaGetSymbolAddress((void**)&fc2H, g_fc2H); cudaGetSymbolAddress((void**)&fc2L, g_fc2L);
    cudaGetSymbolAddress((void**)&atxH, g_atxH); cudaGetSymbolAddress((void**)&atxL, g_atxL);
    cudaGetSymbolAddress((void**)&cbxH, g_cbxH); cudaGetSymbolAddress((void**)&cbxL, g_cbxL);
    cudaGetSymbolAddress((void**)&linH, g_linH); cudaGetSymbolAddress((void**)&linL, g_linL);
    cudaGetSymbolAddress((void**)&XpH, g_XpH);   cudaGetSymbolAddress((void**)&XpL, g_XpL);

    unsigned *cbhH, *cbhL, *wihH, *wihL;
    cudaGetSymbolAddress((void**)&cbhH, g_cbhH); cudaGetSymbolAddress((void**)&cbhL, g_cbhL);
    cudaGetSymbolAddress((void**)&wihH, g_wihH); cudaGetSymbolAddress((void**)&wihL, g_wihL);

    // ---- setup: weight splits ----
    split(fc_w, 2048, 1024, 512, fcwH, fcwL);
    split(fc2_w, 10000, 5000, 512, fc2H, fc2L);
    split(attn_w, 1024, 256, 512, atxH, atxL);           // attn_w[:, :512]
    split(comb_w, 1024, 256, 512, cbxH, cbxL);           // comb_w[:, :512]
    split(comb_w + 512, 1024, 256, 512, cbhH, cbhL);     // comb_w[:, 512:]
    split(gru_wih, 512, 256, 1536, wihH, wihL);
    split(lin_w, 1024, 512, 1024, linH, linL);
    wpack_split_kernel<<<2048, 256>>>(gru_whh, attn_w);

    // ---- conv (direct, fp32) + fc + BN ----
    conv_kernel<<<256, 256>>>(features, conv_w, conv_b);
    hgemm(pXc, 2048, fcwH, fcwL, 1024, fc_b, nullptr, pF0, HH, BB, HH, 2048, 0);
    bn_kernel<<<HH, 256>>>(bn_g, bn_b);

    // ---- captions GEMM + gather(+split) + xA/xC ----
    hgemm(captions, VV, fc2H, fc2L, 5000, fc2_b, nullptr, pEmb, EE, TTOT, EE, VV, 0);
    gather_split_kernel<<<TT * BB, 256>>>(pack_idx);
    pgemm(XpH, XpL, 256, atxH, atxL, 256, attn_b, nullptr, pxA, HH, TT * BB, HH, EE, 0);
    pgemm(XpH, XpL, 256, cbxH, cbxL, 256, comb_b, nullptr, pxC, HH, TT * BB, HH, EE, 0);

    // ---- init hidden state ----
    init_hx_kernel<<<BB, HH>>>(states);

    // ---- persistent fused scan (48 steps, 1 launch) ----
    scan_kernel<<<NBLK, 128>>>(lengths, gru_bih, gru_bhh, hiddens);

    // ---- head ----
    cat_kernel<<<BB, 1024>>>(hiddens);
    hgemm(pCat, 1024, linH, linL, 512, lin_b, nullptr, pY, 1024, BB, 1024, 1024, 1);
    head_kernel<<<BB, 256>>>(lin3_w, lin3_b, out);
}

// round 6
// speedup vs baseline: 1.1038x; 1.1038x over previous
#include <cuda_runtime.h>
#include <cuda_bf16.h>
#include <math.h>

#define BB 256
#define HH 512
#define EE 512
#define VV 10000
#define TT 48
#define TTOT 9436

// ---------------- scratch (device globals; no allocation allowed) -------------
__device__ float g_Xc[BB * 2048];          // conv output flattened [B,2048]
__device__ float g_F0[BB * HH];            // pre-BN fc output
__device__ float g_F[BB * HH];             // BN'd features
__device__ float g_Emb[TTOT * EE];         // packed caption embeddings
__device__ float g_xA[TT * BB * HH];
__device__ float g_xC[TT * BB * HH];
__device__ float g_hx[BB * HH];
__device__ float g_GhL[BB * 2048];         // [Gh(1536) | attn logits h-part(512)]
__device__ float g_Gi[BB * 3 * HH];
__device__ float g_applied[BB * HH];
__device__ float g_inp[BB * HH];
__device__ float g_Cat[BB * 2 * HH];
__device__ float g_Y[BB * 2 * HH];

// pre-split packed bf16 weight buffers (H = hi, L = lo), k packed 2/uint
__device__ unsigned g_fcwH[512 * 1024],  g_fcwL[512 * 1024];    // fc_w K=2048
__device__ unsigned g_fc2H[512 * 5000],  g_fc2L[512 * 5000];    // fc2_w K=10000
__device__ unsigned g_atxH[512 * 256],   g_atxL[512 * 256];     // attn_w[:, :512]
__device__ unsigned g_cbxH[512 * 256],   g_cbxL[512 * 256];     // comb_w[:, :512]
__device__ unsigned g_cbhH[512 * 256],   g_cbhL[512 * 256];     // comb_w[:, 512:]
__device__ unsigned g_wihH[1536 * 256],  g_wihL[1536 * 256];    // gru_wih
__device__ unsigned g_linH[1024 * 512],  g_linL[1024 * 512];    // lin_w K=1024
__device__ unsigned g_wpkH[2048 * 256],  g_wpkL[2048 * 256];    // [whh ; attn_wh]
__device__ unsigned g_XpH[TT * BB * 256], g_XpL[TT * BB * 256]; // split Xpad

// ---------------- bf16 helpers -------------------------------------------------
__device__ __forceinline__ void mma_bf16(float c[4],
    unsigned a0, unsigned a1, unsigned a2, unsigned a3,
    unsigned b0, unsigned b1)
{
    asm volatile(
        "mma.sync.aligned.m16n8k16.row.col.f32.bf16.bf16.f32 "
        "{%0,%1,%2,%3}, {%4,%5,%6,%7}, {%8,%9}, {%0,%1,%2,%3};"
        : "+f"(c[0]), "+f"(c[1]), "+f"(c[2]), "+f"(c[3])
        : "r"(a0), "r"(a1), "r"(a2), "r"(a3), "r"(b0), "r"(b1));
}

__device__ __forceinline__ void split2(float a, float b, unsigned& h, unsigned& l)
{
    __nv_bfloat16 ha = __float2bfloat16_rn(a), hb = __float2bfloat16_rn(b);
    __nv_bfloat16 la = __float2bfloat16_rn(a - __bfloat162float(ha));
    __nv_bfloat16 lb = __float2bfloat16_rn(b - __bfloat162float(hb));
    __nv_bfloat162 th = __halves2bfloat162(ha, hb);
    __nv_bfloat162 tl = __halves2bfloat162(la, lb);
    h = *reinterpret_cast<unsigned*>(&th);
    l = *reinterpret_cast<unsigned*>(&tl);
}

__device__ __forceinline__ void split4u(const float4 v,
    unsigned& h0, unsigned& h1, unsigned& l0, unsigned& l1)
{
    split2(v.x, v.y, h0, l0);
    split2(v.z, v.w, h1, l1);
}

// =================== 64x64 GEMM compute core ===============
#define GEMM_COMPUTE()                                                          \
    {                                                                           \
        unsigned ah[2][4], al_[2][4], bh[4][2], bl[4][2];                       \
        _Pragma("unroll")                                                       \
        for (int mt = 0; mt < 2; mt++) {                                        \
            int r = wm + mt * 16 + krow;                                        \
            int o0 = r * 12 + kcol;                                             \
            int o1 = (r + 8) * 12 + kcol;                                       \
            ah[mt][0] = Ah[o0];     ah[mt][1] = Ah[o1];                         \
            ah[mt][2] = Ah[o0 + 4]; ah[mt][3] = Ah[o1 + 4];                     \
            al_[mt][0] = Al[o0];     al_[mt][1] = Al[o1];                       \
            al_[mt][2] = Al[o0 + 4]; al_[mt][3] = Al[o1 + 4];                   \
        }                                                                       \
        _Pragma("unroll")                                                       \
        for (int nt = 0; nt < 4; nt++) {                                        \
            int cn = wn + nt * 8 + krow;                                        \
            int o = cn * 12 + kcol;                                             \
            bh[nt][0] = Wh[o]; bh[nt][1] = Wh[o + 4];                           \
            bl[nt][0] = Wl[o]; bl[nt][1] = Wl[o + 4];                           \
        }                                                                       \
        _Pragma("unroll")                                                       \
        for (int mt = 0; mt < 2; mt++)                                          \
            _Pragma("unroll")                                                   \
            for (int nt = 0; nt < 4; nt++) {                                    \
                mma_bf16(acc[mt][nt], ah[mt][0], ah[mt][1], ah[mt][2],          \
                         ah[mt][3], bh[nt][0], bh[nt][1]);                      \
                mma_bf16(acc[mt][nt], ah[mt][0], ah[mt][1], ah[mt][2],          \
                         ah[mt][3], bl[nt][0], bl[nt][1]);                      \
                mma_bf16(acc[mt][nt], al_[mt][0], al_[mt][1], al_[mt][2],       \
                         al_[mt][3], bh[nt][0], bh[nt][1]);                     \
            }                                                                   \
    }

// =================== 128x128 GEMM compute core (8 warps, warp tile 64x32) ======
#define GEMM_COMPUTE_128()                                                      \
    {                                                                           \
        unsigned ah[4][4], al_[4][4], bh[4][2], bl[4][2];                       \
        _Pragma("unroll")                                                       \
        for (int mt = 0; mt < 4; mt++) {                                        \
            int r = wm + mt * 16 + krow;                                        \
            int o0 = r * 12 + kcol;                                             \
            int o1 = (r + 8) * 12 + kcol;                                       \
            ah[mt][0] = Ah[o0];     ah[mt][1] = Ah[o1];                         \
            ah[mt][2] = Ah[o0 + 4]; ah[mt][3] = Ah[o1 + 4];                     \
            al_[mt][0] = Al[o0];     al_[mt][1] = Al[o1];                       \
            al_[mt][2] = Al[o0 + 4]; al_[mt][3] = Al[o1 + 4];                   \
        }                                                                       \
        _Pragma("unroll")                                                       \
        for (int nt = 0; nt < 4; nt++) {                                        \
            int cn = wn + nt * 8 + krow;                                        \
            int o = cn * 12 + kcol;                                             \
            bh[nt][0] = Wh[o]; bh[nt][1] = Wh[o + 4];                           \
            bl[nt][0] = Wl[o]; bl[nt][1] = Wl[o + 4];                           \
        }                                                                       \
        _Pragma("unroll")                                                       \
        for (int mt = 0; mt < 4; mt++)                                          \
            _Pragma("unroll")                                                   \
            for (int nt = 0; nt < 4; nt++) {                                    \
                mma_bf16(acc[mt][nt], ah[mt][0], ah[mt][1], ah[mt][2],          \
                         ah[mt][3], bh[nt][0], bh[nt][1]);                      \
                mma_bf16(acc[mt][nt], ah[mt][0], ah[mt][1], ah[mt][2],          \
                         ah[mt][3], bl[nt][0], bl[nt][1]);                      \
                mma_bf16(acc[mt][nt], al_[mt][0], al_[mt][1], al_[mt][2],       \
                         al_[mt][3], bh[nt][0], bh[nt][1]);                     \
            }                                                                   \
    }

#define GEMM_EPILOGUE_128()                                                     \
    _Pragma("unroll")                                                           \
    for (int mt = 0; mt < 4; mt++) {                                            \
        _Pragma("unroll")                                                       \
        for (int nt = 0; nt < 4; nt++) {                                        \
            int r0 = m0 + wm + mt * 16 + (lane >> 2);                           \
            int c0 = n0 + wn + nt * 8 + (lane & 3) * 2;                         \
            _Pragma("unroll")                                                   \
            for (int i = 0; i < 4; i++) {                                       \
                int row = r0 + (i >> 1) * 8;                                    \
                int col = c0 + (i & 1);                                         \
                if (row >= M) continue;                                         \
                float v = acc[mt][nt][i];                                       \
                if (bias) v += bias[col];                                       \
                if (act)  v = fmaxf(v, 0.f);                                    \
                C[(size_t)row * ldc + col] = v;                                 \
            }                                                                   \
        }                                                                       \
    }

// ---------------- hgemm 64x64: A fp32 (split in-kernel), W pre-split -----------
__global__ __launch_bounds__(128) void hgemm_kernel(
    const float* __restrict__ A, int lda,
    const unsigned* __restrict__ WhP, const unsigned* __restrict__ WlP, int ldwU,
    const float* __restrict__ bias,
    const float* __restrict__ add,
    float* __restrict__ C, int ldc,
    int M, int N, int K, int act)
{
    __shared__ unsigned Ah[64 * 12], Al[64 * 12];
    __shared__ unsigned Wh[64 * 12], Wl[64 * 12];

    const int tid  = threadIdx.x;
    const int lane = tid & 31;
    const int warp = tid >> 5;
    const int wm = (warp & 1) * 32;
    const int wn = (warp >> 1) * 32;
    const int m0 = blockIdx.y * 64;
    const int n0 = blockIdx.x * 64;
    const int lr = tid >> 2;
    const int lc = (tid & 3) * 4;
    const int lcu = lc >> 1;
    const int krow = lane >> 2;
    const int kcol = lane & 3;

    float acc[2][4][4];
#pragma unroll
    for (int mt = 0; mt < 2; mt++)
#pragma unroll
        for (int nt = 0; nt < 4; nt++)
#pragma unroll
            for (int i = 0; i < 4; i++) acc[mt][nt][i] = 0.f;

    const int ar0 = m0 + lr, ar1 = m0 + lr + 32;
    const int wr0 = n0 + lr, wr1 = n0 + lr + 32;
    const float4 z4 = make_float4(0.f, 0.f, 0.f, 0.f);

    float4 av0, av1;
    uint2 wv0h, wv0l, wv1h, wv1l;
    av0 = (ar0 < M) ? *(const float4*)(A + (size_t)ar0 * lda + lc) : z4;
    av1 = (ar1 < M) ? *(const float4*)(A + (size_t)ar1 * lda + lc) : z4;
    wv0h = *(const uint2*)(WhP + (size_t)wr0 * ldwU + lcu);
    wv0l = *(const uint2*)(WlP + (size_t)wr0 * ldwU + lcu);
    wv1h = *(const uint2*)(WhP + (size_t)wr1 * ldwU + lcu);
    wv1l = *(const uint2*)(WlP + (size_t)wr1 * ldwU + lcu);

    for (int kk = 0; kk < K; kk += 16) {
        {
            unsigned h0, h1, l0, l1;
            split4u(av0, h0, h1, l0, l1);
            *(uint2*)&Ah[lr * 12 + lcu] = make_uint2(h0, h1);
            *(uint2*)&Al[lr * 12 + lcu] = make_uint2(l0, l1);
            split4u(av1, h0, h1, l0, l1);
            *(uint2*)&Ah[(lr + 32) * 12 + lcu] = make_uint2(h0, h1);
            *(uint2*)&Al[(lr + 32) * 12 + lcu] = make_uint2(l0, l1);
            *(uint2*)&Wh[lr * 12 + lcu] = wv0h;
            *(uint2*)&Wl[lr * 12 + lcu] = wv0l;
            *(uint2*)&Wh[(lr + 32) * 12 + lcu] = wv1h;
            *(uint2*)&Wl[(lr + 32) * 12 + lcu] = wv1l;
        }
        __syncthreads();

        if (kk + 16 < K) {
            int k2 = kk + 16 + lc;
            int k2u = k2 >> 1;
            av0 = (ar0 < M) ? *(const float4*)(A + (size_t)ar0 * lda + k2) : z4;
            av1 = (ar1 < M) ? *(const float4*)(A + (size_t)ar1 * lda + k2) : z4;
            wv0h = *(const uint2*)(WhP + (size_t)wr0 * ldwU + k2u);
            wv0l = *(const uint2*)(WlP + (size_t)wr0 * ldwU + k2u);
            wv1h = *(const uint2*)(WhP + (size_t)wr1 * ldwU + k2u);
            wv1l = *(const uint2*)(WlP + (size_t)wr1 * ldwU + k2u);
        }

        GEMM_COMPUTE();
        __syncthreads();
    }

#pragma unroll
    for (int mt = 0; mt < 2; mt++) {
#pragma unroll
        for (int nt = 0; nt < 4; nt++) {
            int r0 = m0 + wm + mt * 16 + (lane >> 2);
            int c0 = n0 + wn + nt * 8 + (lane & 3) * 2;
#pragma unroll
            for (int i = 0; i < 4; i++) {
                int row = r0 + (i >> 1) * 8;
                int col = c0 + (i & 1);
                if (row >= M) continue;
                float v = acc[mt][nt][i];
                if (bias) v += bias[col];
                if (add)  v += add[(size_t)row * ldc + col];
                if (act)  v = fmaxf(v, 0.f);
                C[(size_t)row * ldc + col] = v;
            }
        }
    }
}

// ---------------- hgemm 128x128: A fp32 (split in-kernel), W pre-split ---------
__global__ __launch_bounds__(256) void hgemm128_kernel(
    const float* __restrict__ A, int lda,
    const unsigned* __restrict__ WhP, const unsigned* __restrict__ WlP, int ldwU,
    const float* __restrict__ bias,
    float* __restrict__ C, int ldc,
    int M, int N, int K, int act)
{
    __shared__ unsigned Ah[128 * 12], Al[128 * 12];
    __shared__ unsigned Wh[128 * 12], Wl[128 * 12];

    const int tid  = threadIdx.x;
    const int lane = tid & 31;
    const int warp = tid >> 5;
    const int wm = (warp & 1) * 64;
    const int wn = (warp >> 1) * 32;
    const int m0 = blockIdx.y * 128;
    const int n0 = blockIdx.x * 128;
    const int lr = tid >> 1;              // 0..127
    const int lc = (tid & 1) * 8;         // 0 or 8 (floats)
    const int lcu = lc >> 1;              // 0 or 4 (uints)
    const int krow = lane >> 2;
    const int kcol = lane & 3;

    float acc[4][4][4];
#pragma unroll
    for (int mt = 0; mt < 4; mt++)
#pragma unroll
        for (int nt = 0; nt < 4; nt++)
#pragma unroll
            for (int i = 0; i < 4; i++) acc[mt][nt][i] = 0.f;

    const int ar = m0 + lr;
    const int wr = n0 + lr;
    const float4 z4 = make_float4(0.f, 0.f, 0.f, 0.f);

    float4 av0, av1;
    uint4 wvh, wvl;
    av0 = (ar < M) ? *(const float4*)(A + (size_t)ar * lda + lc) : z4;
    av1 = (ar < M) ? *(const float4*)(A + (size_t)ar * lda + lc + 4) : z4;
    wvh = *(const uint4*)(WhP + (size_t)wr * ldwU + lcu);
    wvl = *(const uint4*)(WlP + (size_t)wr * ldwU + lcu);

    for (int kk = 0; kk < K; kk += 16) {
        {
            unsigned h0, h1, l0, l1, h2, h3, l2, l3;
            split4u(av0, h0, h1, l0, l1);
            split4u(av1, h2, h3, l2, l3);
            *(uint4*)&Ah[lr * 12 + lcu] = make_uint4(h0, h1, h2, h3);
            *(uint4*)&Al[lr * 12 + lcu] = make_uint4(l0, l1, l2, l3);
            *(uint4*)&Wh[lr * 12 + lcu] = wvh;
            *(uint4*)&Wl[lr * 12 + lcu] = wvl;
        }
        __syncthreads();

        if (kk + 16 < K) {
            int k2 = kk + 16 + lc;
            int k2u = k2 >> 1;
            av0 = (ar < M) ? *(const float4*)(A + (size_t)ar * lda + k2) : z4;
            av1 = (ar < M) ? *(const float4*)(A + (size_t)ar * lda + k2 + 4) : z4;
            wvh = *(const uint4*)(WhP + (size_t)wr * ldwU + k2u);
            wvl = *(const uint4*)(WlP + (size_t)wr * ldwU + k2u);
        }

        GEMM_COMPUTE_128();
        __syncthreads();
    }
    GEMM_EPILOGUE_128();
}

// ---------------- pgemm 128x128: A pre-split, W pre-split ----------------------
__global__ __launch_bounds__(256) void pgemm128_kernel(
    const unsigned* __restrict__ AhP, const unsigned* __restrict__ AlP, int ldaU,
    const unsigned* __restrict__ WhP, const unsigned* __restrict__ WlP, int ldwU,
    const float* __restrict__ bias,
    float* __restrict__ C, int ldc,
    int M, int N, int K, int act)
{
    __shared__ unsigned Ah[128 * 12], Al[128 * 12];
    __shared__ unsigned Wh[128 * 12], Wl[128 * 12];

    const int tid  = threadIdx.x;
    const int lane = tid & 31;
    const int warp = tid >> 5;
    const int wm = (warp & 1) * 64;
    const int wn = (warp >> 1) * 32;
    const int m0 = blockIdx.y * 128;
    const int n0 = blockIdx.x * 128;
    const int lr = tid >> 1;
    const int lcu = (tid & 1) * 4;
    const int krow = lane >> 2;
    const int kcol = lane & 3;

    float acc[4][4][4];
#pragma unroll
    for (int mt = 0; mt < 4; mt++)
#pragma unroll
        for (int nt = 0; nt < 4; nt++)
#pragma unroll
            for (int i = 0; i < 4; i++) acc[mt][nt][i] = 0.f;

    const int ar = m0 + lr;
    const int wr = n0 + lr;

    uint4 avh, avl, wvh, wvl;
    avh = *(const uint4*)(AhP + (size_t)ar * ldaU + lcu);
    avl = *(const uint4*)(AlP + (size_t)ar * ldaU + lcu);
    wvh = *(const uint4*)(WhP + (size_t)wr * ldwU + lcu);
    wvl = *(const uint4*)(WlP + (size_t)wr * ldwU + lcu);

    for (int kk = 0; kk < K; kk += 16) {
        *(uint4*)&Ah[lr * 12 + lcu] = avh;
        *(uint4*)&Al[lr * 12 + lcu] = avl;
        *(uint4*)&Wh[lr * 12 + lcu] = wvh;
        *(uint4*)&Wl[lr * 12 + lcu] = wvl;
        __syncthreads();

        if (kk + 16 < K) {
            int k2u = (kk + 16) / 2 + lcu;
            avh = *(const uint4*)(AhP + (size_t)ar * ldaU + k2u);
            avl = *(const uint4*)(AlP + (size_t)ar * ldaU + k2u);
            wvh = *(const uint4*)(WhP + (size_t)wr * ldwU + k2u);
            wvl = *(const uint4*)(WlP + (size_t)wr * ldwU + k2u);
        }

        GEMM_COMPUTE_128();
        __syncthreads();
    }
    GEMM_EPILOGUE_128();
}

// ---------------- weight split kernels ------------------------------------------
__global__ void split_kernel(const float* __restrict__ src, int srcLd, int colsU,
                             long total, unsigned* __restrict__ H, unsigned* __restrict__ L)
{
    long i = (long)blockIdx.x * 256 + threadIdx.x;
    if (i >= total) return;
    long r = i / colsU;
    int c = (int)(i - r * colsU);
    float a = src[r * srcLd + 2 * c];
    float b = src[r * srcLd + 2 * c + 1];
    split2(a, b, H[i], L[i]);
}

__global__ void wpack_split_kernel(const float* __restrict__ whh,
                                   const float* __restrict__ attn_w)
{
    int i = blockIdx.x * 256 + threadIdx.x;      // 2048*256
    int r = i >> 8, c = i & 255;
    float a, b;
    if (r < 1536) { a = whh[r * 512 + 2 * c]; b = whh[r * 512 + 2 * c + 1]; }
    else { a = attn_w[(r - 1536) * 1024 + 512 + 2 * c];
           b = attn_w[(r - 1536) * 1024 + 512 + 2 * c + 1]; }
    split2(a, b, g_wpkH[i], g_wpkL[i]);
}

// ---------------- direct conv: features[B,2048,8,8] * conv_w[32,2048,3,3], pad1
__global__ __launch_bounds__(256) void conv_kernel(
    const float* __restrict__ features,
    const float* __restrict__ conv_w,
    const float* __restrict__ conv_b)
{
    __shared__ float sF[4][4][100];
    __shared__ float sW[4][4][32][9];
    __shared__ float sRed[2][64][32];

    const int b = blockIdx.x;
    const int tid = threadIdx.x;
    const int qid = tid >> 6;
    const int t2  = tid & 63;
    const int coutg = t2 >> 4;
    const int sg    = t2 & 15;

    for (int e = tid; e < 4 * 4 * 100; e += 256)
        (&sF[0][0][0])[e] = 0.f;

    int fb[4];
#pragma unroll
    for (int sp = 0; sp < 4; sp++) {
        int s = sg * 4 + sp;
        fb[sp] = (s >> 3) * 10 + (s & 7);
    }

    float acc[8][4];
#pragma unroll
    for (int co = 0; co < 8; co++)
#pragma unroll
        for (int sp = 0; sp < 4; sp++) acc[co][sp] = 0.f;

    for (int cbase = 0; cbase < 512; cbase += 4) {
        __syncthreads();
        for (int e = tid; e < 1024; e += 256) {
            int q = e >> 8, c = (e >> 6) & 3, s = e & 63;
            int y = s >> 3, x = s & 7;
            int cin = q * 512 + cbase + c;
            sF[q][c][(y + 1) * 10 + (x + 1)] =
                features[((size_t)b * 2048 + cin) * 64 + s];
        }
        for (int e = tid; e < 4608; e += 256) {
            int q = e / 1152, r = e % 1152;
            int c = r / 288, r2 = r % 288;
            int cout = r2 / 9, k = r2 % 9;
            int cin = q * 512 + cbase + c;
            sW[q][c][cout][k] = conv_w[((size_t)cout * 2048 + cin) * 9 + k];
        }
        __syncthreads();

#pragma unroll
        for (int c = 0; c < 4; c++) {
            const float* fp = &sF[qid][c][0];
            const float* wp = &sW[qid][c][0][0];
#pragma unroll
            for (int ky = 0; ky < 3; ky++) {
#pragma unroll
                for (int kx = 0; kx < 3; kx++) {
                    float wv[8];
#pragma unroll
                    for (int co = 0; co < 8; co++)
                        wv[co] = wp[(coutg * 8 + co) * 9 + ky * 3 + kx];
#pragma unroll
                    for (int sp = 0; sp < 4; sp++) {
                        float fv = fp[fb[sp] + ky * 10 + kx];
#pragma unroll
                        for (int co = 0; co < 8; co++)
                            acc[co][sp] += fv * wv[co];
                    }
                }
            }
        }
    }

    __syncthreads();
    if (qid >= 2) {
#pragma unroll
        for (int co = 0; co < 8; co++)
#pragma unroll
            for (int sp = 0; sp < 4; sp++)
                sRed[qid - 2][t2][co * 4 + sp] = acc[co][sp];
    }
    __syncthreads();
    if (qid < 2) {
#pragma unroll
        for (int co = 0; co < 8; co++)
#pragma unroll
            for (int sp = 0; sp < 4; sp++)
                acc[co][sp] += sRed[qid][t2][co * 4 + sp];
    }
    __syncthreads();
    if (qid == 1) {
#pragma unroll
        for (int co = 0; co < 8; co++)
#pragma unroll
            for (int sp = 0; sp < 4; sp++)
                sRed[0][t2][co * 4 + sp] = acc[co][sp];
    }
    __syncthreads();
    if (qid == 0) {
#pragma unroll
        for (int co = 0; co < 8; co++) {
            int cout = coutg * 8 + co;
            float bval = conv_b[cout];
#pragma unroll
            for (int sp = 0; sp < 4; sp++) {
                int s = sg * 4 + sp;
                g_Xc[(size_t)b * 2048 + cout * 64 + s] =
                    acc[co][sp] + sRed[0][t2][co * 4 + sp] + bval;
            }
        }
    }
}

// ---------------- BatchNorm1d with batch stats ---------------------------------
__global__ void bn_kernel(const float* __restrict__ bn_g,
                          const float* __restrict__ bn_b)
{
    __shared__ float red[256];
    const int h = blockIdx.x;
    const int b = threadIdx.x;
    float v = g_F0[(size_t)b * HH + h];
    red[b] = v;
    __syncthreads();
    for (int s = 128; s > 0; s >>= 1) {
        if (b < s) red[b] += red[b + s];
        __syncthreads();
    }
    float mu = red[0] / 256.f;
    __syncthreads();
    float d = v - mu;
    red[b] = d * d;
    __syncthreads();
    for (int s = 128; s > 0; s >>= 1) {
        if (b < s) red[b] += red[b + s];
        __syncthreads();
    }
    float var = red[0] / 256.f;
    float scale = rsqrtf(var + 1e-5f);
    g_F[(size_t)b * HH + h] = d * scale * bn_g[h] + bn_b[h];
}

// ---------------- gather packed embeddings into split bf16 Xpad ----------------
__global__ void gather_split_kernel(const int* __restrict__ pack_idx)
{
    int tb = blockIdx.x;
    int t = tb >> 8, b = tb & 255;
    int cu = threadIdx.x;
    int idx = pack_idx[b * TT + t];
    float a = 0.f, vb = 0.f;
    if (idx >= 0) {
        a  = g_Emb[(size_t)idx * EE + 2 * cu];
        vb = g_Emb[(size_t)idx * EE + 2 * cu + 1];
    }
    unsigned h, l;
    split2(a, vb, h, l);
    size_t o = (size_t)tb * 256 + cu;
    g_XpH[o] = h; g_XpL[o] = l;
}

__global__ void init_hx_kernel(const float* __restrict__ states)
{
    int i = blockIdx.x * blockDim.x + threadIdx.x;
    g_hx[i] = states[i];
}

// ---------------- softmax over h + attention gating ----------------------------
__global__ void softmax_applied_kernel(int t)
{
    __shared__ float red[512];
    const int b = blockIdx.x;
    const int h = threadIdx.x;
    float v = g_GhL[(size_t)b * 2048 + 1536 + h]
            + g_xA[((size_t)t * BB + b) * HH + h];
    red[h] = v;
    __syncthreads();
    for (int s = 256; s > 0; s >>= 1) {
        if (h < s) red[h] = fmaxf(red[h], red[h + s]);
        __syncthreads();
    }
    float mx = red[0];
    __syncthreads();
    float e = expf(v - mx);
    red[h] = e;
    __syncthreads();
    for (int s = 256; s > 0; s >>= 1) {
        if (h < s) red[h] += red[h + s];
        __syncthreads();
    }
    float aw = e / red[0];
    g_applied[(size_t)b * HH + h] = g_F[(size_t)b * HH + h] * aw;
}

// ---------------- GRU gate combine + hidden update + capture -------------------
__global__ void gru_gate_kernel(const int* __restrict__ lengths,
                                const float* __restrict__ gru_bhh,
                                float* __restrict__ hiddens, int t)
{
    const int b = blockIdx.x;
    const int h = threadIdx.x;
    size_t oG = (size_t)b * 2048;
    size_t oI = (size_t)b * 1536;
    float hr = g_GhL[oG + h]         + gru_bhh[h];
    float hz = g_GhL[oG + 512 + h]   + gru_bhh[512 + h];
    float hn = g_GhL[oG + 1024 + h]  + gru_bhh[1024 + h];
    float ir = g_Gi[oI + h];
    float iz = g_Gi[oI + 512 + h];
    float in_ = g_Gi[oI + 1024 + h];
    float r = 1.f / (1.f + expf(-(ir + hr)));
    float z = 1.f / (1.f + expf(-(iz + hz)));
    float n = tanhf(in_ + r * hn);
    float hprev = g_hx[(size_t)b * HH + h];
    float hnew = (1.f - z) * n + z * hprev;
    g_hx[(size_t)b * HH + h] = hnew;
    if (t == lengths[b] - 1)
        hiddens[(size_t)b * HH + h] = hnew;
}

// ---------------- build concat [hiddens, F] ------------------------------------
__global__ void cat_kernel(const float* __restrict__ hiddens)
{
    const int b = blockIdx.x;
    const int i = threadIdx.x;
    float v = (i < 512) ? hiddens[(size_t)b * HH + i]
                        : g_F[(size_t)b * HH + (i - 512)];
    g_Cat[(size_t)b * 1024 + i] = v;
}

// ---------------- final linear(1024->1) + sigmoid ------------------------------
__global__ void head_kernel(const float* __restrict__ lin3_w,
                            const float* __restrict__ lin3_b,
                            float* __restrict__ out)
{
    __shared__ float red[256];
    const int b = blockIdx.x;
    const int tid = threadIdx.x;
    float acc = 0.f;
#pragma unroll
    for (int k = 0; k < 4; k++) {
        int idx = tid + k * 256;
        acc += g_Y[(size_t)b * 1024 + idx] * lin3_w[idx];
    }
    red[tid] = acc;
    __syncthreads();
    for (int s = 128; s > 0; s >>= 1) {
        if (tid < s) red[tid] += red[tid + s];
        __syncthreads();
    }
    if (tid == 0) {
        float x = red[0] + lin3_b[0];
        out[b] = 1.f / (1.f + expf(-x));
    }
}

// ---------------- host orchestration ------------------------------------------
static void hgemm(const float* A, int lda, const unsigned* WH, const unsigned* WL,
                  int ldwU, const float* bias, const float* add,
                  float* C, int ldc, int M, int N, int K, int act)
{
    dim3 grid(N / 64, (M + 63) / 64);
    hgemm_kernel<<<grid, 128>>>(A, lda, WH, WL, ldwU, bias, add, C, ldc, M, N, K, act);
}

static void hgemm128(const float* A, int lda, const unsigned* WH, const unsigned* WL,
                     int ldwU, const float* bias,
                     float* C, int ldc, int M, int N, int K, int act)
{
    dim3 grid(N / 128, (M + 127) / 128);
    hgemm128_kernel<<<grid, 256>>>(A, lda, WH, WL, ldwU, bias, C, ldc, M, N, K, act);
}

static void pgemm128(const unsigned* AH, const unsigned* AL, int ldaU,
                     const unsigned* WH, const unsigned* WL, int ldwU,
                     const float* bias,
                     float* C, int ldc, int M, int N, int K, int act)
{
    dim3 grid(N / 128, (M + 127) / 128);
    pgemm128_kernel<<<grid, 256>>>(AH, AL, ldaU, WH, WL, ldwU, bias, C, ldc, M, N, K, act);
}

static void split(const float* src, int srcLd, int colsU, long rows,
                  unsigned* H, unsigned* L)
{
    long total = rows * colsU;
    split_kernel<<<(unsigned)((total + 255) / 256), 256>>>(src, srcLd, colsU, total, H, L);
}

extern "C" void kernel_launch(void* const* d_in, const int* in_sizes, int n_in,
                              void* d_out, int out_size)
{
    const float* features = (const float*)d_in[0];
    const float* captions = (const float*)d_in[1];
    const float* states   = (const float*)d_in[2];
    const int*   pack_idx = (const int*)d_in[3];
    const int*   lengths  = (const int*)d_in[4];
    const float* conv_w   = (const float*)d_in[5];
    const float* conv_b   = (const float*)d_in[6];
    const float* fc_w     = (const float*)d_in[7];
    const float* fc_b     = (const float*)d_in[8];
    const float* bn_g     = (const float*)d_in[9];
    const float* bn_b     = (const float*)d_in[10];
    const float* fc2_w    = (const float*)d_in[11];
    const float* fc2_b    = (const float*)d_in[12];
    const float* attn_w   = (const float*)d_in[13];
    const float* attn_b   = (const float*)d_in[14];
    const float* comb_w   = (const float*)d_in[15];
    const float* comb_b   = (const float*)d_in[16];
    const float* gru_wih  = (const float*)d_in[17];
    const float* gru_whh  = (const float*)d_in[18];
    const float* gru_bih  = (const float*)d_in[19];
    const float* gru_bhh  = (const float*)d_in[20];
    const float* lin_w    = (const float*)d_in[21];
    const float* lin_b    = (const float*)d_in[22];
    const float* lin3_w   = (const float*)d_in[23];
    const float* lin3_b   = (const float*)d_in[24];

    float* out = (float*)d_out;            // [0:256) sigmoid, [256: ) hiddens
    float* hiddens = out + 256;

    float *pXc, *pF0, *pEmb, *pxA, *pxC, *phx, *pGhL, *pGi;
    float *pApplied, *pInp, *pCat, *pY;
    unsigned *fcwH, *fcwL, *fc2H, *fc2L, *atxH, *atxL, *cbxH, *cbxL;
    unsigned *cbhH, *cbhL, *wihH, *wihL, *linH, *linL, *wpkH, *wpkL, *XpH, *XpL;
    cudaGetSymbolAddress((void**)&pXc, g_Xc);
    cudaGetSymbolAddress((void**)&pF0, g_F0);
    cudaGetSymbolAddress((void**)&pEmb, g_Emb);
    cudaGetSymbolAddress((void**)&pxA, g_xA);
    cudaGetSymbolAddress((void**)&pxC, g_xC);
    cudaGetSymbolAddress((void**)&phx, g_hx);
    cudaGetSymbolAddress((void**)&pGhL, g_GhL);
    cudaGetSymbolAddress((void**)&pGi, g_Gi);
    cudaGetSymbolAddress((void**)&pApplied, g_applied);
    cudaGetSymbolAddress((void**)&pInp, g_inp);
    cudaGetSymbolAddress((void**)&pCat, g_Cat);
    cudaGetSymbolAddress((void**)&pY, g_Y);
    cudaGetSymbolAddress((void**)&fcwH, g_fcwH); cudaGetSymbolAddress((void**)&fcwL, g_fcwL);
    cudaGetSymbolAddress((void**)&fc2H, g_fc2H); cudaGetSymbolAddress((void**)&fc2L, g_fc2L);
    cudaGetSymbolAddress((void**)&atxH, g_atxH); cudaGetSymbolAddress((void**)&atxL, g_atxL);
    cudaGetSymbolAddress((void**)&cbxH, g_cbxH); cudaGetSymbolAddress((void**)&cbxL, g_cbxL);
    cudaGetSymbolAddress((void**)&cbhH, g_cbhH); cudaGetSymbolAddress((void**)&cbhL, g_cbhL);
    cudaGetSymbolAddress((void**)&wihH, g_wihH); cudaGetSymbolAddress((void**)&wihL, g_wihL);
    cudaGetSymbolAddress((void**)&linH, g_linH); cudaGetSymbolAddress((void**)&linL, g_linL);
    cudaGetSymbolAddress((void**)&wpkH, g_wpkH); cudaGetSymbolAddress((void**)&wpkL, g_wpkL);
    cudaGetSymbolAddress((void**)&XpH, g_XpH);   cudaGetSymbolAddress((void**)&XpL, g_XpL);

    // ---- setup: weight splits ----
    split(fc_w, 2048, 1024, 512, fcwH, fcwL);
    split(fc2_w, 10000, 5000, 512, fc2H, fc2L);
    split(attn_w, 1024, 256, 512, atxH, atxL);           // attn_w[:, :512]
    split(comb_w, 1024, 256, 512, cbxH, cbxL);           // comb_w[:, :512]
    split(comb_w + 512, 1024, 256, 512, cbhH, cbhL);     // comb_w[:, 512:]
    split(gru_wih, 512, 256, 1536, wihH, wihL);
    split(lin_w, 1024, 512, 1024, linH, linL);
    wpack_split_kernel<<<2048, 256>>>(gru_whh, attn_w);

    // ---- conv (direct, fp32) + fc + BN ----
    conv_kernel<<<256, 256>>>(features, conv_w, conv_b);
    hgemm(pXc, 2048, fcwH, fcwL, 1024, fc_b, nullptr, pF0, HH, BB, HH, 2048, 0);
    bn_kernel<<<HH, 256>>>(bn_g, bn_b);

    // ---- captions GEMM (128-tile) + gather(+split) + xA/xC (128-tile) ----
    hgemm128(captions, VV, fc2H, fc2L, 5000, fc2_b, pEmb, EE, TTOT, EE, VV, 0);
    gather_split_kernel<<<TT * BB, 256>>>(pack_idx);
    pgemm128(XpH, XpL, 256, atxH, atxL, 256, attn_b, pxA, HH, TT * BB, HH, EE, 0);
    pgemm128(XpH, XpL, 256, cbxH, cbxL, 256, comb_b, pxC, HH, TT * BB, HH, EE, 0);

    // ---- init hidden state ----
    init_hx_kernel<<<BB, HH>>>(states);

    // ---- sequential scan: 5 launches per step ----
    for (int t = 0; t < TT; t++) {
        hgemm(phx, HH, wpkH, wpkL, 256, nullptr, nullptr, pGhL, 2048, BB, 2048, HH, 0);
        softmax_applied_kernel<<<BB, HH>>>(t);
        hgemm(pApplied, HH, cbhH, cbhL, 256, nullptr,
              pxC + (size_t)t * BB * HH, pInp, HH, BB, HH, HH, 1);
        hgemm(pInp, HH, wihH, wihL, 256, gru_bih, nullptr, pGi, 1536, BB, 1536, HH, 0);
        gru_gate_kernel<<<BB, HH>>>(lengths, gru_bhh, hiddens, t);
    }

    // ---- head ----
    cat_kernel<<<BB, 1024>>>(hiddens);
    hgemm(pCat, 1024, linH, linL, 512, lin_b, nullptr, pY, 1024, BB, 1024, 1024, 1);
    head_kernel<<<BB, 256>>>(lin3_w, lin3_b, out);
}

// round 7
// speedup vs baseline: 1.2840x; 1.1632x over previous
#include <cuda_runtime.h>
#include <cuda_bf16.h>
#include <math.h>

#define BB 256
#define HH 512
#define EE 512
#define VV 10000
#define TT 48
#define TTOT 9436

// ---------------- scratch (device globals; no allocation allowed) -------------
__device__ float g_Xc[BB * 2048];          // conv output flattened [B,2048]
__device__ float g_F0[BB * HH];            // pre-BN fc output
__device__ float g_F[BB * HH];             // BN'd features
__device__ float g_Emb[TTOT * EE];         // packed caption embeddings
__device__ float g_Xpad[TT * BB * EE];     // padded [T,B,E]
__device__ float g_xA[TT * BB * HH];       // x_t @ attn_w_x^T + attn_b
__device__ float g_xC[TT * BB * HH];       // x_t @ comb_w_x^T + comb_b
__device__ float g_hx[BB * HH];
__device__ float g_GhL[BB * 2048];         // [Gh(1536) | attn logits h-part(512)]
__device__ float g_Gi[BB * 3 * HH];
__device__ float g_applied[BB * HH];
__device__ float g_inp[BB * HH];
__device__ float g_Cat[BB * 2 * HH];
__device__ float g_Y[BB * 2 * HH];
__device__ float g_Wpack[2048 * 512];      // rows 0..1535: gru_whh; 1536..2047: attn_w[:,512:]
__device__ float g_Xt[16384 * 2048];       // transposed features [b*64+s][cin]
__device__ float g_CW[320 * 2048];         // conv weights remapped [co*9+tap][cin]
__device__ float g_ConvC[16384 * 320];     // per-tap conv partial sums

// ---------------- bf16 helpers -------------------------------------------------
__device__ __forceinline__ void mma_bf16(float c[4],
    unsigned a0, unsigned a1, unsigned a2, unsigned a3,
    unsigned b0, unsigned b1)
{
    asm volatile(
        "mma.sync.aligned.m16n8k16.row.col.f32.bf16.bf16.f32 "
        "{%0,%1,%2,%3}, {%4,%5,%6,%7}, {%8,%9}, {%0,%1,%2,%3};"
        : "+f"(c[0]), "+f"(c[1]), "+f"(c[2]), "+f"(c[3])
        : "r"(a0), "r"(a1), "r"(a2), "r"(a3), "r"(b0), "r"(b1));
}

// split float4 into packed bf16x2 hi/lo pairs (2 uints each)
__device__ __forceinline__ void split4(const float4 v,
    unsigned& h0, unsigned& h1, unsigned& l0, unsigned& l1)
{
    float f[4] = {v.x, v.y, v.z, v.w};
    __nv_bfloat16 hb[4], lb[4];
#pragma unroll
    for (int i = 0; i < 4; i++) {
        hb[i] = __float2bfloat16_rn(f[i]);
        lb[i] = __float2bfloat16_rn(f[i] - __bfloat162float(hb[i]));
    }
    __nv_bfloat162 t;
    t = __halves2bfloat162(hb[0], hb[1]); h0 = *reinterpret_cast<unsigned*>(&t);
    t = __halves2bfloat162(hb[2], hb[3]); h1 = *reinterpret_cast<unsigned*>(&t);
    t = __halves2bfloat162(lb[0], lb[1]); l0 = *reinterpret_cast<unsigned*>(&t);
    t = __halves2bfloat162(lb[2], lb[3]); l1 = *reinterpret_cast<unsigned*>(&t);
}

// ---------------- BF16x3 GEMM: C[M,N] = A[M,K] @ W[N,K]^T (+bias)(+add)(relu)
// BM=BN=64, BK=16, 128 threads (4 warps, 2x2), warp tile 32x32.
// Requires: N % 64 == 0, K % 16 == 0, lda/ldw % 4 == 0. M guarded.
__global__ __launch_bounds__(128) void tgemm_kernel(
    const float* __restrict__ A, int lda,
    const float* __restrict__ W, int ldw,
    const float* __restrict__ bias,
    const float* __restrict__ add,
    float* __restrict__ C, int ldc,
    int M, int N, int K, int act)
{
    __shared__ unsigned Ah[64 * 12], Al[64 * 12];
    __shared__ unsigned Wh[64 * 12], Wl[64 * 12];

    const int tid  = threadIdx.x;
    const int lane = tid & 31;
    const int warp = tid >> 5;
    const int wm = (warp & 1) * 32;
    const int wn = (warp >> 1) * 32;
    const int m0 = blockIdx.y * 64;
    const int n0 = blockIdx.x * 64;

    const int lr = tid >> 2;          // 0..31 -> rows lr, lr+32
    const int lc = (tid & 3) * 4;     // k offset 0,4,8,12 (floats)
    const int lcu = lc >> 1;          // uint col 0,2,4,6

    float acc[2][4][4];
#pragma unroll
    for (int mt = 0; mt < 2; mt++)
#pragma unroll
        for (int nt = 0; nt < 4; nt++)
#pragma unroll
            for (int i = 0; i < 4; i++) acc[mt][nt][i] = 0.f;

    const int ar0 = m0 + lr, ar1 = m0 + lr + 32;
    const int wr0 = n0 + lr, wr1 = n0 + lr + 32;

    float4 av0, av1, wv0, wv1;
    const float4 z4 = make_float4(0.f, 0.f, 0.f, 0.f);

    av0 = (ar0 < M) ? *(const float4*)(A + (size_t)ar0 * lda + lc) : z4;
    av1 = (ar1 < M) ? *(const float4*)(A + (size_t)ar1 * lda + lc) : z4;
    wv0 = *(const float4*)(W + (size_t)wr0 * ldw + lc);
    wv1 = *(const float4*)(W + (size_t)wr1 * ldw + lc);

    const int krow = lane >> 2;   // 0..7
    const int kcol = lane & 3;    // 0..3 (uint cols; pairs k=2c,2c+1)

    for (int kk = 0; kk < K; kk += 16) {
        // split + store prefetched tile
        {
            unsigned h0, h1, l0, l1;
            split4(av0, h0, h1, l0, l1);
            *(uint2*)&Ah[lr * 12 + lcu] = make_uint2(h0, h1);
            *(uint2*)&Al[lr * 12 + lcu] = make_uint2(l0, l1);
            split4(av1, h0, h1, l0, l1);
            *(uint2*)&Ah[(lr + 32) * 12 + lcu] = make_uint2(h0, h1);
            *(uint2*)&Al[(lr + 32) * 12 + lcu] = make_uint2(l0, l1);
            split4(wv0, h0, h1, l0, l1);
            *(uint2*)&Wh[lr * 12 + lcu] = make_uint2(h0, h1);
            *(uint2*)&Wl[lr * 12 + lcu] = make_uint2(l0, l1);
            split4(wv1, h0, h1, l0, l1);
            *(uint2*)&Wh[(lr + 32) * 12 + lcu] = make_uint2(h0, h1);
            *(uint2*)&Wl[(lr + 32) * 12 + lcu] = make_uint2(l0, l1);
        }
        __syncthreads();

        // prefetch next tile
        if (kk + 16 < K) {
            int k2 = kk + 16 + lc;
            av0 = (ar0 < M) ? *(const float4*)(A + (size_t)ar0 * lda + k2) : z4;
            av1 = (ar1 < M) ? *(const float4*)(A + (size_t)ar1 * lda + k2) : z4;
            wv0 = *(const float4*)(W + (size_t)wr0 * ldw + k2);
            wv1 = *(const float4*)(W + (size_t)wr1 * ldw + k2);
        }

        // compute: one k16 step, 24 MMAs per warp
        unsigned ah[2][4], al_[2][4], bh[4][2], bl[4][2];
#pragma unroll
        for (int mt = 0; mt < 2; mt++) {
            int r = wm + mt * 16 + krow;
            int o0 = r * 12 + kcol;
            int o1 = (r + 8) * 12 + kcol;
            ah[mt][0] = Ah[o0];     ah[mt][1] = Ah[o1];
            ah[mt][2] = Ah[o0 + 4]; ah[mt][3] = Ah[o1 + 4];
            al_[mt][0] = Al[o0];     al_[mt][1] = Al[o1];
            al_[mt][2] = Al[o0 + 4]; al_[mt][3] = Al[o1 + 4];
        }
#pragma unroll
        for (int nt = 0; nt < 4; nt++) {
            int cn = wn + nt * 8 + krow;
            int o = cn * 12 + kcol;
            bh[nt][0] = Wh[o]; bh[nt][1] = Wh[o + 4];
            bl[nt][0] = Wl[o]; bl[nt][1] = Wl[o + 4];
        }
#pragma unroll
        for (int mt = 0; mt < 2; mt++)
#pragma unroll
            for (int nt = 0; nt < 4; nt++) {
                mma_bf16(acc[mt][nt], ah[mt][0], ah[mt][1], ah[mt][2], ah[mt][3],
                         bh[nt][0], bh[nt][1]);
                mma_bf16(acc[mt][nt], ah[mt][0], ah[mt][1], ah[mt][2], ah[mt][3],
                         bl[nt][0], bl[nt][1]);
                mma_bf16(acc[mt][nt], al_[mt][0], al_[mt][1], al_[mt][2], al_[mt][3],
                         bh[nt][0], bh[nt][1]);
            }
        __syncthreads();
    }

    // epilogue
#pragma unroll
    for (int mt = 0; mt < 2; mt++) {
#pragma unroll
        for (int nt = 0; nt < 4; nt++) {
            int r0 = m0 + wm + mt * 16 + (lane >> 2);
            int c0 = n0 + wn + nt * 8 + (lane & 3) * 2;
#pragma unroll
            for (int i = 0; i < 4; i++) {
                int row = r0 + (i >> 1) * 8;
                int col = c0 + (i & 1);
                if (row >= M) continue;
                float v = acc[mt][nt][i];
                if (bias) v += bias[col];
                if (add)  v += add[(size_t)row * ldc + col];
                if (act)  v = fmaxf(v, 0.f);
                C[(size_t)row * ldc + col] = v;
            }
        }
    }
}

// ---------------- pack [gru_whh ; attn_w[:,512:]] into g_Wpack [2048,512] ------
__global__ void pack_kernel(const float* __restrict__ whh,
                            const float* __restrict__ attn_w)
{
    int i = blockIdx.x * 256 + threadIdx.x;      // 0 .. 2048*512-1
    int row = i >> 9, k = i & 511;
    float v;
    if (row < 1536) v = whh[i];
    else            v = attn_w[(row - 1536) * 1024 + 512 + k];
    g_Wpack[i] = v;
}

// ---------------- features transpose: [b][cin][s] -> Xt[(b*64+s)][cin] (fp32) --
__global__ __launch_bounds__(256) void feat_transpose_kernel(
    const float* __restrict__ features)
{
    __shared__ float sm[32][65];
    const int b = blockIdx.x >> 6;          // 0..255
    const int cg = blockIdx.x & 63;         // 0..63 (32 cins each)
    const int tid = threadIdx.x;

    for (int i = tid; i < 32 * 64; i += 256) {
        int c = i >> 6, s = i & 63;
        sm[c][s] = features[((size_t)b * 2048 + cg * 32 + c) * 64 + s];
    }
    __syncthreads();
    for (int j = tid; j < 64 * 32; j += 256) {
        int s = j >> 5, c = j & 31;
        g_Xt[((size_t)b * 64 + s) * 2048 + cg * 32 + c] = sm[c][s];
    }
}

// ---------------- conv weight remap: CW[co*9+tap][cin]; rows 288..319 zero -----
__global__ void convw_pack_kernel(const float* __restrict__ conv_w)
{
    int i = blockIdx.x * 256 + threadIdx.x;      // 320*2048
    int r = i >> 11, c = i & 2047;
    float v = 0.f;
    if (r < 288) {
        int co = r / 9, tap = r % 9;
        v = conv_w[((size_t)co * 2048 + c) * 9 + tap];
    }
    g_CW[i] = v;
}

// ---------------- conv tap-reduce: Xc[b][co*64+s] = bias + sum of 9 taps -------
__global__ void conv_reduce_kernel(const float* __restrict__ conv_b)
{
    int i = blockIdx.x * 256 + threadIdx.x;      // 256*2048
    int b = i >> 11;
    int r = i & 2047;
    int co = r >> 6;
    int s = r & 63;
    int y = s >> 3, x = s & 7;
    float acc = conv_b[co];
#pragma unroll
    for (int ky = 0; ky < 3; ky++) {
        int yy = y + ky - 1;
        if (yy < 0 || yy > 7) continue;
#pragma unroll
        for (int kx = 0; kx < 3; kx++) {
            int xx = x + kx - 1;
            if (xx < 0 || xx > 7) continue;
            acc += g_ConvC[((size_t)b * 64 + yy * 8 + xx) * 320 + co * 9 + ky * 3 + kx];
        }
    }
    g_Xc[(size_t)b * 2048 + co * 64 + s] = acc;
}

// ---------------- BatchNorm1d with batch stats ---------------------------------
__global__ void bn_kernel(const float* __restrict__ bn_g,
                          const float* __restrict__ bn_b)
{
    __shared__ float red[256];
    const int h = blockIdx.x;
    const int b = threadIdx.x;
    float v = g_F0[(size_t)b * HH + h];
    red[b] = v;
    __syncthreads();
    for (int s = 128; s > 0; s >>= 1) {
        if (b < s) red[b] += red[b + s];
        __syncthreads();
    }
    float mu = red[0] / 256.f;
    __syncthreads();
    float d = v - mu;
    red[b] = d * d;
    __syncthreads();
    for (int s = 128; s > 0; s >>= 1) {
        if (b < s) red[b] += red[b + s];
        __syncthreads();
    }
    float var = red[0] / 256.f;
    float scale = rsqrtf(var + 1e-5f);
    g_F[(size_t)b * HH + h] = d * scale * bn_g[h] + bn_b[h];
}

// ---------------- gather packed embeddings into padded [T,B,E] -----------------
__global__ void gather_kernel(const int* __restrict__ pack_idx)
{
    int tb = blockIdx.x;
    int t = tb >> 8, b = tb & 255;
    int e = threadIdx.x;
    int idx = pack_idx[b * TT + t];
    float v = (idx >= 0) ? g_Emb[(size_t)idx * EE + e] : 0.f;
    g_Xpad[(size_t)tb * EE + e] = v;
}

__global__ void init_hx_kernel(const float* __restrict__ states)
{
    int i = blockIdx.x * blockDim.x + threadIdx.x;
    g_hx[i] = states[i];
}

// ---------------- softmax over h + attention gating (reads GhL L-part + xA) ----
__global__ void softmax_applied_kernel(int t)
{
    __shared__ float red[512];
    const int b = blockIdx.x;
    const int h = threadIdx.x;
    float v = g_GhL[(size_t)b * 2048 + 1536 + h]
            + g_xA[((size_t)t * BB + b) * HH + h];
    red[h] = v;
    __syncthreads();
    for (int s = 256; s > 0; s >>= 1) {
        if (h < s) red[h] = fmaxf(red[h], red[h + s]);
        __syncthreads();
    }
    float mx = red[0];
    __syncthreads();
    float e = expf(v - mx);
    red[h] = e;
    __syncthreads();
    for (int s = 256; s > 0; s >>= 1) {
        if (h < s) red[h] += red[h + s];
        __syncthreads();
    }
    float aw = e / red[0];
    g_applied[(size_t)b * HH + h] = g_F[(size_t)b * HH + h] * aw;
}

// ---------------- GRU gate combine + hidden update + capture at t==len-1 -------
__global__ void gru_gate_kernel(const int* __restrict__ lengths,
                                const float* __restrict__ gru_bhh,
                                float* __restrict__ hiddens, int t)
{
    const int b = blockIdx.x;
    const int h = threadIdx.x;
    size_t oG = (size_t)b * 2048;
    size_t oI = (size_t)b * 1536;
    float hr = g_GhL[oG + h]         + gru_bhh[h];
    float hz = g_GhL[oG + 512 + h]   + gru_bhh[512 + h];
    float hn = g_GhL[oG + 1024 + h]  + gru_bhh[1024 + h];
    float ir = g_Gi[oI + h];
    float iz = g_Gi[oI + 512 + h];
    float in_ = g_Gi[oI + 1024 + h];
    float r = 1.f / (1.f + expf(-(ir + hr)));
    float z = 1.f / (1.f + expf(-(iz + hz)));
    float n = tanhf(in_ + r * hn);
    float hprev = g_hx[(size_t)b * HH + h];
    float hnew = (1.f - z) * n + z * hprev;
    g_hx[(size_t)b * HH + h] = hnew;
    if (t == lengths[b] - 1)
        hiddens[(size_t)b * HH + h] = hnew;
}

// ---------------- build concat [hiddens, F] ------------------------------------
__global__ void cat_kernel(const float* __restrict__ hiddens)
{
    const int b = blockIdx.x;
    const int i = threadIdx.x;
    float v = (i < 512) ? hiddens[(size_t)b * HH + i]
                        : g_F[(size_t)b * HH + (i - 512)];
    g_Cat[(size_t)b * 1024 + i] = v;
}

// ---------------- final linear(1024->1) + sigmoid ------------------------------
__global__ void head_kernel(const float* __restrict__ lin3_w,
                            const float* __restrict__ lin3_b,
                            float* __restrict__ out)
{
    __shared__ float red[256];
    const int b = blockIdx.x;
    const int tid = threadIdx.x;
    float acc = 0.f;
#pragma unroll
    for (int k = 0; k < 4; k++) {
        int idx = tid + k * 256;
        acc += g_Y[(size_t)b * 1024 + idx] * lin3_w[idx];
    }
    red[tid] = acc;
    __syncthreads();
    for (int s = 128; s > 0; s >>= 1) {
        if (tid < s) red[tid] += red[tid + s];
        __syncthreads();
    }
    if (tid == 0) {
        float x = red[0] + lin3_b[0];
        out[b] = 1.f / (1.f + expf(-x));
    }
}

// ---------------- host orchestration ------------------------------------------
static void tgemm(const float* A, int lda, const float* W, int ldw,
                  const float* bias, const float* add,
                  float* C, int ldc, int M, int N, int K, int act)
{
    dim3 grid(N / 64, (M + 63) / 64);
    tgemm_kernel<<<grid, 128>>>(A, lda, W, ldw, bias, add, C, ldc, M, N, K, act);
}

extern "C" void kernel_launch(void* const* d_in, const int* in_sizes, int n_in,
                              void* d_out, int out_size)
{
    const float* features = (const float*)d_in[0];
    const float* captions = (const float*)d_in[1];
    const float* states   = (const float*)d_in[2];
    const int*   pack_idx = (const int*)d_in[3];
    const int*   lengths  = (const int*)d_in[4];
    const float* conv_w   = (const float*)d_in[5];
    const float* conv_b   = (const float*)d_in[6];
    const float* fc_w     = (const float*)d_in[7];
    const float* fc_b     = (const float*)d_in[8];
    const float* bn_g     = (const float*)d_in[9];
    const float* bn_b     = (const float*)d_in[10];
    const float* fc2_w    = (const float*)d_in[11];
    const float* fc2_b    = (const float*)d_in[12];
    const float* attn_w   = (const float*)d_in[13];
    const float* attn_b   = (const float*)d_in[14];
    const float* comb_w   = (const float*)d_in[15];
    const float* comb_b   = (const float*)d_in[16];
    const float* gru_wih  = (const float*)d_in[17];
    const float* gru_whh  = (const float*)d_in[18];
    const float* gru_bih  = (const float*)d_in[19];
    const float* gru_bhh  = (const float*)d_in[20];
    const float* lin_w    = (const float*)d_in[21];
    const float* lin_b    = (const float*)d_in[22];
    const float* lin3_w   = (const float*)d_in[23];
    const float* lin3_b   = (const float*)d_in[24];

    float* out = (float*)d_out;            // [0:256) sigmoid, [256: ) hiddens
    float* hiddens = out + 256;

    float *pXc, *pF0, *pEmb, *pXpad, *pxA, *pxC, *phx, *pGhL, *pGi;
    float *pApplied, *pInp, *pCat, *pY, *pWpack, *pXt, *pCW, *pConvC;
    cudaGetSymbolAddress((void**)&pXc, g_Xc);
    cudaGetSymbolAddress((void**)&pF0, g_F0);
    cudaGetSymbolAddress((void**)&pEmb, g_Emb);
    cudaGetSymbolAddress((void**)&pXpad, g_Xpad);
    cudaGetSymbolAddress((void**)&pxA, g_xA);
    cudaGetSymbolAddress((void**)&pxC, g_xC);
    cudaGetSymbolAddress((void**)&phx, g_hx);
    cudaGetSymbolAddress((void**)&pGhL, g_GhL);
    cudaGetSymbolAddress((void**)&pGi, g_Gi);
    cudaGetSymbolAddress((void**)&pApplied, g_applied);
    cudaGetSymbolAddress((void**)&pInp, g_inp);
    cudaGetSymbolAddress((void**)&pCat, g_Cat);
    cudaGetSymbolAddress((void**)&pY, g_Y);
    cudaGetSymbolAddress((void**)&pWpack, g_Wpack);
    cudaGetSymbolAddress((void**)&pXt, g_Xt);
    cudaGetSymbolAddress((void**)&pCW, g_CW);
    cudaGetSymbolAddress((void**)&pConvC, g_ConvC);

    // launches 0-4 (cheap, independent) — so launch #5 (ncu capture) = captions GEMM
    pack_kernel<<<(2048 * 512) / 256, 256>>>(gru_whh, attn_w);            // 0
    feat_transpose_kernel<<<256 * 64, 256>>>(features);                   // 1
    convw_pack_kernel<<<(320 * 2048) / 256, 256>>>(conv_w);               // 2
    init_hx_kernel<<<BB, HH>>>(states);                                   // 3
    // conv as GEMM: [16384 x 320 x 2048]                                  // 4
    tgemm(pXt, 2048, pCW, 2048, nullptr, nullptr, pConvC, 320, 16384, 320, 2048, 0);
    // captions GEMM (PROFILED LAUNCH #5)
    tgemm(captions, VV, fc2_w, VV, fc2_b, nullptr, pEmb, EE, TTOT, EE, VV, 0);
    // conv tap reduce -> Xc                                               // 6
    conv_reduce_kernel<<<2048, 256>>>(conv_b);
    // fc + BN
    tgemm(pXc, 2048, fc_w, 2048, fc_b, nullptr, pF0, HH, BB, HH, 2048, 0);
    bn_kernel<<<HH, 256>>>(bn_g, bn_b);
    // gather + x-part precompute GEMMs
    gather_kernel<<<TT * BB, EE>>>(pack_idx);
    tgemm(pXpad, EE, attn_w, 1024, attn_b, nullptr, pxA, HH, TT * BB, HH, EE, 0);
    tgemm(pXpad, EE, comb_w, 1024, comb_b, nullptr, pxC, HH, TT * BB, HH, EE, 0);

    // sequential scan: 5 launches per step
    for (int t = 0; t < TT; t++) {
        tgemm(phx, HH, pWpack, HH, nullptr, nullptr, pGhL, 2048, BB, 2048, HH, 0);
        softmax_applied_kernel<<<BB, HH>>>(t);
        tgemm(pApplied, HH, comb_w + 512, 1024, nullptr,
              pxC + (size_t)t * BB * HH, pInp, HH, BB, HH, HH, 1);
        tgemm(pInp, HH, gru_wih, HH, gru_bih, nullptr, pGi, 1536, BB, 1536, HH, 0);
        gru_gate_kernel<<<BB, HH>>>(lengths, gru_bhh, hiddens, t);
    }

    // head
    cat_kernel<<<BB, 1024>>>(hiddens);
    tgemm(pCat, 1024, lin_w, 1024, lin_b, nullptr, pY, 1024, BB, 1024, 1024, 1);
    head_kernel<<<BB, 256>>>(lin3_w, lin3_b, out);
}